// round 8
// baseline (speedup 1.0000x reference)
#include <cuda_runtime.h>

// NoTradeRegionRNN: D=2 channel RNN scan, T timesteps, B independent lanes.
// x, returns: (D, T, B) row-major. output: (D, T, B) then hT (D, 1, B).
//
// R8 = R7 (one 16B cp.async.cg per thread per step into an S=16 SMEM ring,
// per-warp self-contained so wait_group semantics are exact) with the
// pipeline re-ordered to keep waits off the serial chain:
//   issue(s+15) -> compute(s) -> store(s) -> wait_group<13> -> LDS(s+2)
// and a TWO-deep register buffer (cur = step s, nxt = step s+1), so the
// wait and the 29-cycle LDS latency sit two iterations ahead of use.

__device__ __forceinline__ float relu_(float v) { return fmaxf(v, 0.0f); }
__device__ __forceinline__ float clamp_(float v, float lo, float hi) {
    return fminf(fmaxf(v, lo), hi);
}
__device__ __forceinline__ float frcp_(float v) {
    float r; asm("rcp.approx.f32 %0, %1;" : "=f"(r) : "f"(v)); return r;
}
__device__ __forceinline__ void cp16_(unsigned dst, const void* src) {
    asm volatile("cp.async.cg.shared.global [%0], [%1], 16;" :: "r"(dst), "l"(src));
}
__device__ __forceinline__ void cp_commit_() {
    asm volatile("cp.async.commit_group;");
}
template <int N>
__device__ __forceinline__ void cp_wait_() {
    asm volatile("cp.async.wait_group %0;" :: "n"(N));
}

// ---------------- parameter derivation ----------------
struct Params {
    float ac, bd;
    float Wi0, Wi1, Wh0, Wh1, W10, W11, W20, W21;
    float C_lbx, LO_lbx, HI_lbx;   // val = clamp(fma(a, slope, C), LO, HI)
    float C_ubx, LO_ubx, HI_ubx;
    float C_lby, LO_lby, HI_lby;
    float C_uby, LO_uby, HI_uby;
};

__device__ __forceinline__ Params make_params(
    const float* __restrict__ tgt, const float* __restrict__ wi,
    const float* __restrict__ wh,  const float* __restrict__ bh,
    const float* __restrict__ w1,  const float* __restrict__ w2,
    const float* __restrict__ wr)
{
    Params P;
    const float wr00 = wr[0], wr01 = wr[1], wr10 = wr[2], wr11 = wr[3];
    const float bh0 = bh[0], bh1 = bh[1];
    const float t0 = tgt[0], t1 = tgt[1];
    P.Wi0 = wi[0]; P.Wi1 = wi[1];
    P.Wh0 = wh[0]; P.Wh1 = wh[1];
    P.W10 = w1[0]; P.W11 = w1[1];
    P.W20 = w2[0]; P.W21 = w2[1];
    P.ac = wr10 / wr00;
    P.bd = wr01 / wr11;

    // Corners: k0:(-,-) k1:(-,+) k2:(+,+) k3:(+,-) applied to (bh0, bh1)
    float Cx[4], Cy[4];
    const float s0[4] = {-1.f, -1.f, 1.f, 1.f};
    const float s1[4] = {-1.f,  1.f, 1.f, -1.f};
#pragma unroll
    for (int k = 0; k < 4; ++k) {
        float vx = s0[k] * bh0, vy = s1[k] * bh1;
        Cx[k] = wr00 * vx + wr01 * vy + t0;
        Cy[k] = wr10 * vx + wr11 * vy + t1;
    }
    const bool bdp = (P.bd >= 0.0f);
    const bool acp = (P.ac >= 0.0f);
    // bound: w=(a-c)*slope; val = o - relu(A - relu(w)) == clamp(w+o-A, o-A, o)
    {
        float c = bdp ? Cy[0] : Cy[1], A = fabsf(Cx[1] - Cx[0]), o = bdp ? Cx[1] : Cx[0];
        P.C_lbx = -c * P.bd + o - A; P.LO_lbx = o - A; P.HI_lbx = o;
    }
    {
        float c = bdp ? Cy[3] : Cy[2], A = fabsf(Cx[2] - Cx[3]), o = bdp ? Cx[2] : Cx[3];
        P.C_ubx = -c * P.bd + o - A; P.LO_ubx = o - A; P.HI_ubx = o;
    }
    {
        float c = acp ? Cx[0] : Cx[3], A = fabsf(Cy[0] - Cy[3]), o = acp ? Cy[3] : Cy[0];
        P.C_lby = -c * P.ac + o - A; P.LO_lby = o - A; P.HI_lby = o;
    }
    {
        float c = acp ? Cx[1] : Cx[2], A = fabsf(Cy[1] - Cy[2]), o = acp ? Cy[2] : Cy[1];
        P.C_uby = -c * P.ac + o - A; P.LO_uby = o - A; P.HI_uby = o;
    }
    return P;
}

__device__ __forceinline__ void ntr_step(const Params& P,
                                         float& hx, float& hy,
                                         float rx, float ry,
                                         float xx, float xy)
{
    float denom = fmaf(hx, rx, fmaf(hy, ry, 1.0f));
    float inv = frcp_(denom);
    float ax = fmaf(hx, rx, hx) * inv;      // hx*(1+rx)/denom
    float ay = fmaf(hy, ry, hy) * inv;

    float lbx = clamp_(fmaf(ay, P.bd, P.C_lbx), P.LO_lbx, P.HI_lbx);
    float ubx = clamp_(fmaf(ay, P.bd, P.C_ubx), P.LO_ubx, P.HI_ubx);
    float lby = clamp_(fmaf(ax, P.ac, P.C_lby), P.LO_lby, P.HI_lby);
    float uby = clamp_(fmaf(ax, P.ac, P.C_uby), P.LO_uby, P.HI_uby);

    float g1x = relu_(fmaf(P.Wi0, xx, fmaf(P.Wh0, ax, -lbx)));
    float g1y = relu_(fmaf(P.Wi1, xy, fmaf(P.Wh1, ay, -lby)));
    float g2x = relu_(fmaf(P.W10, g1x, ubx - lbx));
    float g2y = relu_(fmaf(P.W11, g1y, uby - lby));
    hx = fmaf(P.W20, g2x, ubx);
    hy = fmaf(P.W21, g2y, uby);
}

// ---------------- cp.async staged kernel (T=512, B=16384) ----------------
// Stage j (2048 B): warp w region [w*512, +512) holds plane p at [p*128, +128).
// Per step each thread issues ONE 16B cp.async for (plane = lane>>3,
// chunk = lane&7) of its own warp. Planes: 0 r0(t=s), 1 r1, 2 x0(t=s+1), 3 x1.
template <int T, int B>
__global__ void __launch_bounds__(128)
ntr_rnn_cpasync(const float* __restrict__ x,
                const float* __restrict__ ret,
                const float* __restrict__ tgt,
                const float* __restrict__ wi,
                const float* __restrict__ wh,
                const float* __restrict__ bh,
                const float* __restrict__ w1,
                const float* __restrict__ w2,
                const float* __restrict__ wr,
                float* __restrict__ out,
                int write_hT)
{
    constexpr int S = 16;                    // ring stages
    constexpr int STEPS = T - 1;             // 511
    constexpr int MAIN_GROUPS = (STEPS - (S - 1)) / S;   // 31
    constexpr int TAIL = STEPS - MAIN_GROUPS * S;        // 15
    static_assert(MAIN_GROUPS * S + TAIL == STEPS, "");
    static_assert(TAIL >= 2, "tail rotation needs >= 2 steps");

    __shared__ __align__(16) float smem[S * 4 * 128];

    const int tid = threadIdx.x;
    const int b = blockIdx.x * blockDim.x + tid;
    const Params P = make_params(tgt, wi, wh, bh, w1, w2, wr);

    const size_t TB = (size_t)T * (size_t)B;

    // ---- cp.async source/dest for THIS thread ----
    const int w = tid >> 5;          // warp in CTA
    const int m = tid & 31;          // lane
    const int p = m >> 3;            // plane this lane copies
    const int sub = m & 7;           // 16B chunk within the warp's 128B plane
    const float* plane_base =
        (p == 0) ? ret :
        (p == 1) ? ret + TB :
        (p == 2) ? x + B :
                   x + TB + B;
    const float* cp_src = plane_base + (size_t)blockIdx.x * 128 + w * 32 + sub * 4;

    const unsigned smem_base = (unsigned)__cvta_generic_to_shared(smem);
    const unsigned cp_dst0 = smem_base + (unsigned)(w * 512 + p * 128 + sub * 16);
#define STAGE_DST(stg)     (cp_dst0 + (unsigned)(stg) * 2048u)
#define STAGE_VAL(stg, pp) (smem[(stg) * 512 + w * 128 + (pp) * 32 + m])

    // output pointers; step s writes t = s+1
    float* po0 = out + B + b;
    float* po1 = out + TB + B + b;

    // h0 = x[:, 0, :]
    float hx = __ldg(x + b);
    float hy = __ldg(x + TB + b);
    out[b] = hx;
    out[TB + b] = hy;

    // ---- prologue: issue stages for steps 0..S-2 ----
#pragma unroll
    for (int j = 0; j < S - 1; ++j) {
        cp16_(STAGE_DST(j), cp_src + (size_t)j * B);
        cp_commit_();
    }
    cp_wait_<S - 3>();           // steps 0 and 1 have landed
    // cur = step 0, nxt = step 1
    float rx  = STAGE_VAL(0, 0), ry  = STAGE_VAL(0, 1);
    float xx  = STAGE_VAL(0, 2), xy  = STAGE_VAL(0, 3);
    float nrx = STAGE_VAL(1, 0), nry = STAGE_VAL(1, 1);
    float nxx = STAGE_VAL(1, 2), nxy = STAGE_VAL(1, 3);

    // ---- main loop ----
    for (int g = 0; g < MAIN_GROUPS; ++g) {
#pragma unroll
        for (int j = 0; j < S; ++j) {
            // 1. issue step s+S-1 into stage (j-1)&(S-1)
            const int stg_i = (j + S - 1) & (S - 1);
            cp16_(STAGE_DST(stg_i), cp_src + (size_t)(j + S - 1) * B);
            cp_commit_();
            // 2. compute step s from cur registers; store
            ntr_step(P, hx, hy, rx, ry, xx, xy);
            __stcs(po0 + (size_t)j * B, hx);
            __stcs(po1 + (size_t)j * B, hy);
            // 3. wait for step s+2's group, LDS it, rotate buffers
            cp_wait_<S - 3>();
            const int stg_n = (j + 2) & (S - 1);
            rx = nrx; ry = nry; xx = nxx; xy = nxy;
            nrx = STAGE_VAL(stg_n, 0);
            nry = STAGE_VAL(stg_n, 1);
            nxx = STAGE_VAL(stg_n, 2);
            nxy = STAGE_VAL(stg_n, 3);
        }
        cp_src += (size_t)S * B;
        po0 += (size_t)S * B; po1 += (size_t)S * B;
    }

    // ---- tail: TAIL steps, everything already issued; drain once ----
    cp_wait_<0>();
#pragma unroll
    for (int j = 0; j < TAIL; ++j) {
        ntr_step(P, hx, hy, rx, ry, xx, xy);
        __stcs(po0 + (size_t)j * B, hx);
        __stcs(po1 + (size_t)j * B, hy);
        rx = nrx; ry = nry; xx = nxx; xy = nxy;
        if (j + 2 < TAIL) {
            const int stg_n = (j + 2) & (S - 1);
            nrx = STAGE_VAL(stg_n, 0);
            nry = STAGE_VAL(stg_n, 1);
            nxx = STAGE_VAL(stg_n, 2);
            nxy = STAGE_VAL(stg_n, 3);
        }
    }
#undef STAGE_DST
#undef STAGE_VAL

    if (write_hT) {
        out[2 * TB + b] = hx;
        out[2 * TB + B + b] = hy;
    }
}

// ---------------- generic fallback (any T, B) ----------------
__global__ void __launch_bounds__(128)
ntr_rnn_generic(const float* __restrict__ x,
                const float* __restrict__ ret,
                const float* __restrict__ tgt,
                const float* __restrict__ wi,
                const float* __restrict__ wh,
                const float* __restrict__ bh,
                const float* __restrict__ w1,
                const float* __restrict__ w2,
                const float* __restrict__ wr,
                float* __restrict__ out,
                int T, int B, int write_hT)
{
    const int b = blockIdx.x * blockDim.x + threadIdx.x;
    if (b >= B) return;
    const Params P = make_params(tgt, wi, wh, bh, w1, w2, wr);

    const size_t TB = (size_t)T * (size_t)B;
    const float* r0 = ret + b;
    const float* r1 = ret + TB + b;
    const float* x0 = x + b;
    const float* x1 = x + TB + b;
    float* o0 = out + b;
    float* o1 = out + TB + b;

    float hx = __ldg(x0);
    float hy = __ldg(x1);
    o0[0] = hx; o1[0] = hy;

    for (int t = 1; t < T; ++t) {
        size_t offp = (size_t)(t - 1) * B;
        size_t offt = (size_t)t * B;
        float rx = __ldcs(r0 + offp), ry = __ldcs(r1 + offp);
        float xx = __ldcs(x0 + offt), xy = __ldcs(x1 + offt);
        ntr_step(P, hx, hy, rx, ry, xx, xy);
        __stcs(o0 + offt, hx);
        __stcs(o1 + offt, hy);
    }
    if (write_hT) {
        out[2 * TB + b] = hx;
        out[2 * TB + B + b] = hy;
    }
}

extern "C" void kernel_launch(void* const* d_in, const int* in_sizes, int n_in,
                              void* d_out, int out_size)
{
    // 0 input (D,T,B), 1 target, 2 returns (D,T,B), 3 hidden (D,1,B),
    // 4 w_input, 5 w_hidden, 6 b_hidden, 7 w_fc1, 8 w_fc2, 9 w_rotate
    const float* x   = (const float*)d_in[0];
    const float* tgt = (const float*)d_in[1];
    const float* ret = (const float*)d_in[2];
    const float* wi  = (const float*)d_in[4];
    const float* wh  = (const float*)d_in[5];
    const float* bh  = (const float*)d_in[6];
    const float* w1  = (const float*)d_in[7];
    const float* w2  = (const float*)d_in[8];
    const float* wr  = (const float*)d_in[9];
    float* out = (float*)d_out;

    const int D = 2;
    const int B = in_sizes[3] / D;
    const int T = in_sizes[0] / (D * B);
    const int write_hT = (out_size >= D * T * B + D * B) ? 1 : 0;

    constexpr int TS = 512, BS = 16384;
    if (T == TS && B == BS) {
        const int threads = 128;
        const int blocks = BS / threads;     // 128 CTAs
        ntr_rnn_cpasync<TS, BS><<<blocks, threads>>>(
            x, ret, tgt, wi, wh, bh, w1, w2, wr, out, write_hT);
    } else {
        const int threads = 128;
        const int blocks = (B + threads - 1) / threads;
        ntr_rnn_generic<<<blocks, threads>>>(
            x, ret, tgt, wi, wh, bh, w1, w2, wr, out, T, B, write_hT);
    }
}